// round 1
// baseline (speedup 1.0000x reference)
#include <cuda_runtime.h>

#define N_TOK 256
#define D_DIM 128
#define LEAKY_ALPHA 0.2f
#define NEG_INF_V (-9e15f)

static const int THREADS = 512;
// v tile (256*128) + energies (256) + redmax(16) + redsum(16) + partials(512)
static const int SMEM_FLOATS = N_TOK * D_DIM + N_TOK + 16 + 16 + 512;
static const int SMEM_BYTES = SMEM_FLOATS * 4;

__global__ void __launch_bounds__(512, 1)
gat_kernel(const float* __restrict__ q, const float* __restrict__ v,
           const int* __restrict__ mask, const float* __restrict__ W,
           const float* __restrict__ bias, float* __restrict__ out)
{
    extern __shared__ float sm[];
    float* v_sm   = sm;                        // 32768 floats
    float* e_sm   = v_sm + N_TOK * D_DIM;      // 256
    float* redmax = e_sm + N_TOK;              // 16
    float* redsum = redmax + 16;               // 16
    float* part   = redsum + 16;               // 512

    const int row = blockIdx.x;
    const size_t base = (size_t)row * (size_t)(N_TOK * D_DIM);
    const float4* qr = (const float4*)(q + base);
    const float4* vr = (const float4*)(v + base);

    const int tid  = threadIdx.x;
    const int lane = tid & 31;
    const int wid  = tid >> 5;   // 0..15

    // Each lane owns 4 consecutive W entries for q-part and v-part.
    const float4 Wq = ((const float4*)W)[lane];
    const float4 Wv = ((const float4*)W)[32 + lane];

    // ---------------- Phase 1: energies + stage v into smem ----------------
    // Warp `wid` handles rows [wid*16, wid*16+16). Fully coalesced float4
    // streaming loads; rows are independent so unroll gives deep MLP.
    #pragma unroll
    for (int r = 0; r < 16; ++r) {
        const int n = wid * 16 + r;
        float4 q4 = __ldcs(qr + n * 32 + lane);
        float4 v4 = __ldcs(vr + n * 32 + lane);
        float p = q4.x * Wq.x + q4.y * Wq.y + q4.z * Wq.z + q4.w * Wq.w
                + v4.x * Wv.x + v4.y * Wv.y + v4.z * Wv.z + v4.w * Wv.w;
        ((float4*)(v_sm + n * D_DIM))[lane] = v4;
        #pragma unroll
        for (int off = 16; off; off >>= 1)
            p += __shfl_xor_sync(0xffffffffu, p, off);
        if (lane == 0) e_sm[n] = p;
    }
    __syncthreads();

    // ---------------- Phase 2: leaky-relu + mask + softmax ----------------
    float val = -3.4e38f;
    if (tid < N_TOK) {
        float e = e_sm[tid] + bias[0];
        e = (e >= 0.0f) ? e : LEAKY_ALPHA * e;
        const int m = mask[(size_t)row * N_TOK + tid];
        val = (m > 0) ? e : NEG_INF_V;
    }
    // block max
    float mx = val;
    #pragma unroll
    for (int off = 16; off; off >>= 1)
        mx = fmaxf(mx, __shfl_xor_sync(0xffffffffu, mx, off));
    if (lane == 0) redmax[wid] = mx;
    __syncthreads();
    float gmax = redmax[0];
    #pragma unroll
    for (int w = 1; w < 16; ++w) gmax = fmaxf(gmax, redmax[w]);

    // exp + block sum
    float p = (tid < N_TOK) ? __expf(val - gmax) : 0.0f;
    float s = p;
    #pragma unroll
    for (int off = 16; off; off >>= 1)
        s += __shfl_xor_sync(0xffffffffu, s, off);
    if (lane == 0) redsum[wid] = s;
    __syncthreads();
    float tot = 0.0f;
    #pragma unroll
    for (int w = 0; w < 16; ++w) tot += redsum[w];
    const float inv = 1.0f / tot;
    if (tid < N_TOK) e_sm[tid] = p * inv;   // normalized scores
    __syncthreads();

    // ---------------- Phase 3: out[d] = sum_n score[n] * v[n][d] ----------
    // 512 threads = 128 dims x 4 n-groups of 64. smem reads conflict-free.
    const int d = tid & 127;
    const int g = tid >> 7;
    float acc = 0.0f;
    #pragma unroll 8
    for (int k = 0; k < 64; ++k) {
        const int n = g * 64 + k;
        acc += e_sm[n] * v_sm[n * D_DIM + d];
    }
    part[g * 128 + d] = acc;
    __syncthreads();
    if (tid < 128) {
        out[(size_t)row * D_DIM + tid] =
            part[tid] + part[128 + tid] + part[256 + tid] + part[384 + tid];
    }
}

extern "C" void kernel_launch(void* const* d_in, const int* in_sizes, int n_in,
                              void* d_out, int out_size)
{
    const float* q    = (const float*)d_in[0];
    const float* v    = (const float*)d_in[1];
    const int*   mask = (const int*)d_in[2];
    const float* W    = (const float*)d_in[3];
    const float* b    = (const float*)d_in[4];
    float* out = (float*)d_out;

    const int rows = in_sizes[0] / (N_TOK * D_DIM);  // B*N = 2048

    cudaFuncSetAttribute(gat_kernel,
                         cudaFuncAttributeMaxDynamicSharedMemorySize,
                         SMEM_BYTES);
    gat_kernel<<<rows, THREADS, SMEM_BYTES>>>(q, v, mask, W, b, out);
}

// round 2
// speedup vs baseline: 1.1010x; 1.1010x over previous
#include <cuda_runtime.h>

#define N_TOK 256
#define D_DIM 128
#define LEAKY_ALPHA 0.2f
#define NEG_INF_V (-9e15f)

#define NWARP 8
#define NCHAIN 4

__global__ void __launch_bounds__(256, 3)
gat_kernel(const float* __restrict__ q, const float* __restrict__ v,
           const int* __restrict__ mask, const float* __restrict__ W,
           const float* __restrict__ bias, float* __restrict__ out)
{
    __shared__ int   sm_mask[N_TOK];
    __shared__ float wm[NWARP];
    __shared__ float ws[NWARP];
    __shared__ float acc_s[NWARP * D_DIM];

    const int row  = blockIdx.x;
    const int tid  = threadIdx.x;
    const int lane = tid & 31;
    const int wid  = tid >> 5;          // 0..7

    const size_t base = (size_t)row * (size_t)(N_TOK * D_DIM);
    const float4* qr = (const float4*)(q + base);
    const float4* vr = (const float4*)(v + base);

    // preload mask row into smem (broadcast reads later)
    if (tid < N_TOK) sm_mask[tid] = __ldcs(mask + (size_t)row * N_TOK + tid);

    // each lane owns 4 consecutive W entries for the q-part and the v-part
    const float4 Wq = ((const float4*)W)[lane];
    const float4 Wv = ((const float4*)W)[32 + lane];
    const float  bb = bias[0];

    __syncthreads();

    // ---- single streaming pass: energies + online softmax + v accumulate ----
    // warp `wid` owns tokens [wid*32, wid*32+32), split into NCHAIN
    // independent online-softmax chains (merged exactly afterwards).
    float  m_c[NCHAIN], s_c[NCHAIN];
    float4 a_c[NCHAIN];
    #pragma unroll
    for (int c = 0; c < NCHAIN; ++c) {
        m_c[c] = NEG_INF_V;
        s_c[c] = 0.0f;
        a_c[c] = make_float4(0.f, 0.f, 0.f, 0.f);
    }

    const int n0 = wid * 32;
    #pragma unroll
    for (int rg = 0; rg < 32 / NCHAIN; ++rg) {
        float4 q4[NCHAIN], v4[NCHAIN];
        // batch all loads for this round first -> deep MLP
        #pragma unroll
        for (int c = 0; c < NCHAIN; ++c) {
            const int n = n0 + rg * NCHAIN + c;
            q4[c] = __ldcs(qr + n * 32 + lane);
            v4[c] = __ldcs(vr + n * 32 + lane);
        }
        #pragma unroll
        for (int c = 0; c < NCHAIN; ++c) {
            const int n = n0 + rg * NCHAIN + c;
            float p = q4[c].x * Wq.x + q4[c].y * Wq.y
                    + q4[c].z * Wq.z + q4[c].w * Wq.w
                    + v4[c].x * Wv.x + v4[c].y * Wv.y
                    + v4[c].z * Wv.z + v4[c].w * Wv.w;
            #pragma unroll
            for (int off = 16; off; off >>= 1)
                p += __shfl_xor_sync(0xffffffffu, p, off);
            // energy -> leaky relu -> mask
            float e = p + bb;
            e = (e >= 0.0f) ? e : LEAKY_ALPHA * e;
            const float val = (sm_mask[n] > 0) ? e : NEG_INF_V;
            // online softmax update of chain c
            const float m_new = fmaxf(m_c[c], val);
            const float scale = __expf(m_c[c] - m_new);
            const float pe    = __expf(val - m_new);
            s_c[c] = s_c[c] * scale + pe;
            a_c[c].x = a_c[c].x * scale + pe * v4[c].x;
            a_c[c].y = a_c[c].y * scale + pe * v4[c].y;
            a_c[c].z = a_c[c].z * scale + pe * v4[c].z;
            a_c[c].w = a_c[c].w * scale + pe * v4[c].w;
            m_c[c] = m_new;
        }
    }

    // ---- merge chains within the warp (m_c/s_c are warp-uniform) ----
    float M = m_c[0];
    #pragma unroll
    for (int c = 1; c < NCHAIN; ++c) M = fmaxf(M, m_c[c]);
    float  S = 0.0f;
    float4 A = make_float4(0.f, 0.f, 0.f, 0.f);
    #pragma unroll
    for (int c = 0; c < NCHAIN; ++c) {
        const float f = __expf(m_c[c] - M);
        S  += f * s_c[c];
        A.x += f * a_c[c].x;  A.y += f * a_c[c].y;
        A.z += f * a_c[c].z;  A.w += f * a_c[c].w;
    }

    // ---- merge across warps via smem ----
    if (lane == 0) { wm[wid] = M; ws[wid] = S; }
    ((float4*)(acc_s + wid * D_DIM))[lane] = A;
    __syncthreads();

    if (tid < D_DIM) {
        float gm = wm[0];
        #pragma unroll
        for (int w = 1; w < NWARP; ++w) gm = fmaxf(gm, wm[w]);
        float tot = 0.0f, num = 0.0f;
        #pragma unroll
        for (int w = 0; w < NWARP; ++w) {
            const float f = __expf(wm[w] - gm);
            tot += f * ws[w];
            num += f * acc_s[w * D_DIM + tid];
        }
        out[(size_t)row * D_DIM + tid] = num / tot;
    }
}

extern "C" void kernel_launch(void* const* d_in, const int* in_sizes, int n_in,
                              void* d_out, int out_size)
{
    const float* q    = (const float*)d_in[0];
    const float* v    = (const float*)d_in[1];
    const int*   mask = (const int*)d_in[2];
    const float* W    = (const float*)d_in[3];
    const float* b    = (const float*)d_in[4];
    float* out = (float*)d_out;

    const int rows = in_sizes[0] / (N_TOK * D_DIM);  // B*N = 2048

    gat_kernel<<<rows, 256>>>(q, v, mask, W, b, out);
}